// round 4
// baseline (speedup 1.0000x reference)
#include <cuda_runtime.h>
#include <cuda_fp16.h>

// ---------------------------------------------------------------------------
// CharEmbeddingCNN: embed + 3x conv1d(k=3,4,5) + maxpool + relu + len-mask.
//
//   C_kj[c, o] = sum_i W_k[o, i, j] * emb[c, i]      (12 tables, 256x256, fp16)
//   y_k[n,o,t] = b_k[o] + sum_j C_kj[x[n,t+j], o]
//   out[n,o]   = mask(n) * relu(max_{k,t} y_k[n,o,t])
//
// R4: ONE fused kernel. 148 CTAs (1/SM, single wave): build tables in-kernel
// (768 tile-jobs, pipelined SMEM GEMM), software grid barrier (sense-reversing,
// replay-safe), then the R3 lookup/max pool phases.
// ---------------------------------------------------------------------------

#define LSEQ  20
#define NTOT  8192            // 64 * 128
#define NPC   222             // n per CTA (37 groups)
#define NGRP  37
#define OTILES 4              // 4 tiles of 64 outputs
#define TBL_BYTES 32768       // per-table SMEM slice: 256 chars * 64 halves * 2B
#define CHSTRIDE 24           // shorts per n (20 used, padded for uint4)
#define SMEM_CHARS_OFF (5 * TBL_BYTES)
#define SMEM_TOTAL (SMEM_CHARS_OFF + NPC * CHSTRIDE * 2)
#define NCTA  148
#define NJOBS 768             // 12 tables * 8 c-blocks(32) * 8 o-blocks(32)

__device__ __align__(16) __half g_tbl_h[12 * 256 * 256];
__device__ unsigned g_count = 0;
__device__ volatile unsigned g_gen = 0;

// ---------------------------------------------------------------------------
// Build one 32c x 32o x 256k table tile with a 256-thread group.
// Named barrier bar_id scopes syncs to the group. Register-prefetch pipeline.
// Same ascending-k fp32 add order as before -> bit-identical tables.
// ---------------------------------------------------------------------------
__device__ __forceinline__ void build_job(
    int job, float* As, float* Bs,
    const float* __restrict__ emb,
    const float* __restrict__ w3, const float* __restrict__ w4,
    const float* __restrict__ w5,
    int tid_g, int bar_id)
{
    const int tbl = job >> 6;
    const int c0  = ((job >> 3) & 7) * 32;
    const int o0  = (job & 7) * 32;

    int k, j; const float* w;
    if (tbl < 3)      { k = 3; j = tbl;     w = w3; }
    else if (tbl < 7) { k = 4; j = tbl - 3; w = w4; }
    else              { k = 5; j = tbl - 7; w = w5; }
    const int wk = 256 * k;

    const int ty = tid_g >> 4, tx = tid_g & 15;   // 16x16, 2x2 per thread

    float a00 = 0.f, a01 = 0.f, a10 = 0.f, a11 = 0.f;

    float pa[4], pb[4];
    #pragma unroll
    for (int r = 0; r < 4; r++) {
        int idx = tid_g + r * 256;
        int ci = idx >> 5, ki = idx & 31;
        pa[r] = emb[(c0 + ci) * 256 + ki];
        pb[r] = w[(o0 + ci) * wk + ki * k + j];
    }

    for (int chunk = 0; chunk < 8; chunk++) {
        asm volatile("bar.sync %0, 256;" :: "r"(bar_id));   // SMEM free
        #pragma unroll
        for (int r = 0; r < 4; r++) {
            int idx = tid_g + r * 256;
            int ci = idx >> 5, ki = idx & 31;
            As[ki * 34 + ci] = pa[r];
            Bs[ki * 34 + ci] = pb[r];
        }
        asm volatile("bar.sync %0, 256;" :: "r"(bar_id));   // SMEM filled
        if (chunk < 7) {
            int kk = (chunk + 1) * 32;
            #pragma unroll
            for (int r = 0; r < 4; r++) {
                int idx = tid_g + r * 256;
                int ci = idx >> 5, ki = idx & 31;
                pa[r] = emb[(c0 + ci) * 256 + kk + ki];
                pb[r] = w[(o0 + ci) * wk + (kk + ki) * k + j];
            }
        }
        #pragma unroll
        for (int ki = 0; ki < 32; ki++) {
            float2 av = *reinterpret_cast<float2*>(&As[ki * 34 + 2 * ty]);
            float2 bv = *reinterpret_cast<float2*>(&Bs[ki * 34 + 2 * tx]);
            a00 += av.x * bv.x; a01 += av.x * bv.y;
            a10 += av.y * bv.x; a11 += av.y * bv.y;
        }
    }

    const int c = c0 + 2 * ty, o = o0 + 2 * tx;
    __half2 h0 = __floats2half2_rn(a00, a01);
    __half2 h1 = __floats2half2_rn(a10, a11);
    *reinterpret_cast<__half2*>(&g_tbl_h[tbl * 65536 + c * 256 + o])       = h0;
    *reinterpret_cast<__half2*>(&g_tbl_h[tbl * 65536 + (c + 1) * 256 + o]) = h1;
}

// ---------------------------------------------------------------------------
// Pool phase: stage K table slices, lookup+HADD2+HMAX2, fold (max+bias) into
// the cross-phase accumulator.
// ---------------------------------------------------------------------------
template<int K>
__device__ __forceinline__ void run_phase(
    char* sm, const unsigned short* schars,
    const __half* __restrict__ gphase,
    const float* __restrict__ bias,
    __half2 acc[2][4],
    int otile, int n_count, int qtotal,
    int tid, int warp, int n_sub, unsigned lane_off)
{
    __syncthreads();  // previous phase done reading SMEM

    // Stage K table slices: K*256 rows of 64 halves (128B rows). __ldcg:
    // cross-SM-written this launch, read-once.
    const int total16 = K * 2048;          // 16B chunks
    for (int idx = tid; idx < total16; idx += 1024) {
        int j   = idx >> 11;
        int rem = idx & 2047;
        int c   = rem >> 3;
        int f   = rem & 7;
        uint4 v = __ldcg(reinterpret_cast<const uint4*>(
            gphase + j * 65536 + c * 256 + otile * 64 + f * 8));
        *reinterpret_cast<uint4*>(sm + (j * 256 + c) * 128 + f * 16) = v;
    }
    __syncthreads();

    const float* bp = bias + otile * 64 + (lane_off >> 1);
    __half2 bh[4];
    #pragma unroll
    for (int c = 0; c < 4; c++)
        bh[c] = __floats2half2_rn(bp[2 * c], bp[2 * c + 1]);

    const __half2 NEGINF = __float2half2_rn(-60000.0f);

    #pragma unroll
    for (int it = 0; it < 2; it++) {
        const int q = warp + it * 32;
        if (q < qtotal) {
            const int nl  = q * 4 + n_sub;
            const int nlc = (nl < n_count) ? nl : (n_count - 1);

            const unsigned short* cp = schars + nlc * CHSTRIDE;
            uint4 p0 = *reinterpret_cast<const uint4*>(cp);
            uint4 p1 = *reinterpret_cast<const uint4*>(cp + 8);
            uint2 p2 = *reinterpret_cast<const uint2*>(cp + 16);
            unsigned pk[10] = {p0.x, p0.y, p0.z, p0.w,
                               p1.x, p1.y, p1.z, p1.w, p2.x, p2.y};
            unsigned a[LSEQ];
            #pragma unroll
            for (int p = 0; p < LSEQ; p++)
                a[p] = ((pk[p >> 1] >> (16 * (p & 1))) & 0xFFFFu) + lane_off;

            __half2 m0 = NEGINF, m1 = NEGINF, m2 = NEGINF, m3 = NEGINF;
            #pragma unroll
            for (int t = 0; t <= LSEQ - K; t++) {
                uint4 su = *reinterpret_cast<const uint4*>(sm + a[t]);
                __half2 s0 = *reinterpret_cast<__half2*>(&su.x);
                __half2 s1 = *reinterpret_cast<__half2*>(&su.y);
                __half2 s2 = *reinterpret_cast<__half2*>(&su.z);
                __half2 s3 = *reinterpret_cast<__half2*>(&su.w);
                #pragma unroll
                for (int j = 1; j < K; j++) {
                    uint4 ru = *reinterpret_cast<const uint4*>(
                        sm + (unsigned)(j * TBL_BYTES) + a[t + j]);
                    s0 = __hadd2(s0, *reinterpret_cast<__half2*>(&ru.x));
                    s1 = __hadd2(s1, *reinterpret_cast<__half2*>(&ru.y));
                    s2 = __hadd2(s2, *reinterpret_cast<__half2*>(&ru.z));
                    s3 = __hadd2(s3, *reinterpret_cast<__half2*>(&ru.w));
                }
                m0 = __hmax2(m0, s0);
                m1 = __hmax2(m1, s1);
                m2 = __hmax2(m2, s2);
                m3 = __hmax2(m3, s3);
            }

            acc[it][0] = __hmax2(acc[it][0], __hadd2(m0, bh[0]));
            acc[it][1] = __hmax2(acc[it][1], __hadd2(m1, bh[1]));
            acc[it][2] = __hmax2(acc[it][2], __hadd2(m2, bh[2]));
            acc[it][3] = __hmax2(acc[it][3], __hadd2(m3, bh[3]));
        }
    }
}

// ---------------------------------------------------------------------------
__global__ void __launch_bounds__(1024, 1)
fused_cnn_kernel(const int* __restrict__ x, const int* __restrict__ lens,
                 const float* __restrict__ emb,
                 const float* __restrict__ w3, const float* __restrict__ b3,
                 const float* __restrict__ w4, const float* __restrict__ b4,
                 const float* __restrict__ w5, const float* __restrict__ b5,
                 float* __restrict__ out)
{
    extern __shared__ char sm[];
    const int tid     = threadIdx.x;
    const int group   = blockIdx.x;
    const int otile   = blockIdx.y;
    const int bid     = otile * NGRP + group;     // 0..147
    const int n_start = group * NPC;
    const int n_count = min(NTOT - n_start, NPC);

    unsigned short* schars = reinterpret_cast<unsigned short*>(sm + SMEM_CHARS_OFF);

    // ---- char row-offset staging (char * 128B row stride), padded stride 24.
    for (int i = tid; i < n_count * LSEQ; i += 1024) {
        int n = i / LSEQ, p = i - n * LSEQ;
        schars[n * CHSTRIDE + p] =
            (unsigned short)(x[(n_start + n) * LSEQ + p] << 7);
    }

    // ---- table build: 4 groups of 256 threads, scratch in the (not yet
    // used) table SMEM area. slot in [0,592); jobs slot and slot+592.
    {
        const int grp   = tid >> 8;
        const int tid_g = tid & 255;
        float* As = reinterpret_cast<float*>(sm + grp * 8704);  // 32x34 fp32
        float* Bs = As + 32 * 34;
        const int slot = grp * NCTA + bid;                      // < 592
        build_job(slot, As, Bs, emb, w3, w4, w5, tid_g, 1 + grp);
        if (slot + 592 < NJOBS)
            build_job(slot + 592, As, Bs, emb, w3, w4, w5, tid_g, 1 + grp);
    }

    // ---- grid barrier (sense-reversing via generation counter; replay-safe)
    __threadfence();
    __syncthreads();
    if (tid == 0) {
        unsigned gen = g_gen;
        __threadfence();
        if (atomicAdd(&g_count, 1) == NCTA - 1) {
            atomicExch(&g_count, 0);
            __threadfence();
            g_gen = gen + 1;
        } else {
            while (g_gen == gen) { }
        }
    }
    __syncthreads();

    // ---- pool phases
    const int lane  = tid & 31;
    const int warp  = tid >> 5;
    const int n_sub = lane >> 3;
    const unsigned lane_off = (unsigned)((lane & 7) * 16);
    const int qtotal = (n_count + 3) >> 2;

    __half2 acc[2][4];
    #pragma unroll
    for (int i = 0; i < 2; i++)
        #pragma unroll
        for (int c = 0; c < 4; c++) acc[i][c] = __float2half2_rn(0.0f);

    run_phase<3>(sm, schars, g_tbl_h,             b3, acc, otile, n_count, qtotal, tid, warp, n_sub, lane_off);
    run_phase<4>(sm, schars, g_tbl_h + 3 * 65536, b4, acc, otile, n_count, qtotal, tid, warp, n_sub, lane_off);
    run_phase<5>(sm, schars, g_tbl_h + 7 * 65536, b5, acc, otile, n_count, qtotal, tid, warp, n_sub, lane_off);

    // ---- epilogue: one pure store per (n, 8-output slice); masked -> zeros.
    #pragma unroll
    for (int it = 0; it < 2; it++) {
        const int q  = warp + it * 32;
        const int nl = q * 4 + n_sub;
        if (q < qtotal && nl < n_count) {
            const int n = n_start + nl;
            float4 o0 = make_float4(0.f, 0.f, 0.f, 0.f);
            float4 o1 = o0;
            if (lens[n] != 0) {
                float2 f0 = __half22float2(acc[it][0]);
                float2 f1 = __half22float2(acc[it][1]);
                float2 f2 = __half22float2(acc[it][2]);
                float2 f3 = __half22float2(acc[it][3]);
                o0 = make_float4(f0.x, f0.y, f1.x, f1.y);
                o1 = make_float4(f2.x, f2.y, f3.x, f3.y);
            }
            float4* po = reinterpret_cast<float4*>(
                &out[(size_t)n * 256 + otile * 64 + (lane_off >> 1)]);
            po[0] = o0;
            po[1] = o1;
        }
    }
}

// ---------------------------------------------------------------------------
extern "C" void kernel_launch(void* const* d_in, const int* in_sizes, int n_in,
                              void* d_out, int out_size)
{
    const int*   x    = (const int*)  d_in[0];
    const int*   lens = (const int*)  d_in[1];
    const float* emb  = (const float*)d_in[2];
    const float* w3   = (const float*)d_in[3];
    const float* b3   = (const float*)d_in[4];
    const float* w4   = (const float*)d_in[5];
    const float* b4   = (const float*)d_in[6];
    const float* w5   = (const float*)d_in[7];
    const float* b5   = (const float*)d_in[8];
    float* out = (float*)d_out;

    cudaFuncSetAttribute(fused_cnn_kernel,
                         cudaFuncAttributeMaxDynamicSharedMemorySize, SMEM_TOTAL);
    fused_cnn_kernel<<<dim3(NGRP, OTILES), 1024, SMEM_TOTAL>>>(
        x, lens, emb, w3, b3, w4, b4, w5, b5, out);
}